// round 2
// baseline (speedup 1.0000x reference)
#include <cuda_runtime.h>
#include <cstdint>

// Problem constants
#define BB   64      // batch
#define NCQ  5       // questions per sample
#define LQ   20      // question length
#define FF   20      // video frames
#define CC   8192    // video feature dim
#define EE   300     // embed dim
#define HH   512     // hidden
#define G4   2048    // 4*H
#define BT   320     // B*NC

// ---------------- scratch (device globals; allocation-free) ----------------
__device__ float g_GAv[BB * FF * G4];   // video layer1 input preacts [b][f][4H]
__device__ float g_GAt[BT * LQ * G4];   // text  layer1 input preacts [b*nc][l][4H]
__device__ float g_vh1[2][BB * HH];
__device__ float g_vc1[BB * HH];
__device__ float g_vh2[2][BB * HH];
__device__ float g_vc2[BB * HH];
__device__ float g_th1[2][BT * HH];
__device__ float g_tc1[BT * HH];
__device__ float g_th2[2][BT * HH];
__device__ float g_tc2[BT * HH];
__device__ float g_wc[2 * HH];
__device__ float g_bc[1];

__device__ __forceinline__ float sigf(float x) { return 1.0f / (1.0f + __expf(-x)); }

// ---------------- big NT SGEMM: D[m,n] = bias[n] + sum_k A[m,k]*W[n,k] -----
// 128x128x8 tiles, 256 threads, 8x8 microtile.
__global__ __launch_bounds__(256) void sgemm_nt_kernel(
    int M, int N, int K,
    const float* __restrict__ A,
    const float* __restrict__ W,
    const float* __restrict__ bias,
    float* __restrict__ D)
{
    __shared__ float As[8][128];
    __shared__ float Bs[8][128];
    const int m0 = blockIdx.y * 128;
    const int n0 = blockIdx.x * 128;
    const int tid = threadIdx.x;
    const int tx = tid & 15, ty = tid >> 4;

    float acc[8][8];
#pragma unroll
    for (int i = 0; i < 8; i++)
#pragma unroll
        for (int j = 0; j < 8; j++) acc[i][j] = 0.0f;

    const int lrow = tid >> 1;         // 0..127
    const int lk4  = (tid & 1) * 4;    // 0 or 4
    const float* Aptr = A + (size_t)(m0 + lrow) * K + lk4;
    const float* Wptr = W + (size_t)(n0 + lrow) * K + lk4;

    for (int k0 = 0; k0 < K; k0 += 8) {
        float4 av = *(const float4*)(Aptr + k0);
        float4 wv = *(const float4*)(Wptr + k0);
        As[lk4 + 0][lrow] = av.x; As[lk4 + 1][lrow] = av.y;
        As[lk4 + 2][lrow] = av.z; As[lk4 + 3][lrow] = av.w;
        Bs[lk4 + 0][lrow] = wv.x; Bs[lk4 + 1][lrow] = wv.y;
        Bs[lk4 + 2][lrow] = wv.z; Bs[lk4 + 3][lrow] = wv.w;
        __syncthreads();
#pragma unroll
        for (int kk = 0; kk < 8; kk++) {
            float4 a0 = *(const float4*)&As[kk][ty * 8];
            float4 a1 = *(const float4*)&As[kk][ty * 8 + 4];
            float4 b0 = *(const float4*)&Bs[kk][tx * 8];
            float4 b1 = *(const float4*)&Bs[kk][tx * 8 + 4];
            float a[8] = {a0.x, a0.y, a0.z, a0.w, a1.x, a1.y, a1.z, a1.w};
            float b[8] = {b0.x, b0.y, b0.z, b0.w, b1.x, b1.y, b1.z, b1.w};
#pragma unroll
            for (int i = 0; i < 8; i++)
#pragma unroll
                for (int j = 0; j < 8; j++) acc[i][j] += a[i] * b[j];
        }
        __syncthreads();
    }
#pragma unroll
    for (int i = 0; i < 8; i++) {
        int m = m0 + ty * 8 + i;
#pragma unroll
        for (int j = 0; j < 8; j++) {
            int n = n0 + tx * 8 + j;
            D[(size_t)m * N + n] = acc[i][j] + bias[n];
        }
    }
}

// ------------- embedding-gather GEMM (text layer1 input preacts) ----------
// D[m,n] = b[n] + sum_k Ew[q[m],k] * Wt[n,k]; M=6400, N=2048, K=300.
__global__ __launch_bounds__(256) void embgemm_kernel(
    const int* __restrict__ q,
    const float* __restrict__ Ew,
    const float* __restrict__ Wt,
    const float* __restrict__ bias,
    float* __restrict__ D)
{
    __shared__ int qs[64];
    __shared__ float As[8][64];
    __shared__ float Bs[8][64];
    const int m0 = blockIdx.y * 64;
    const int n0 = blockIdx.x * 64;
    const int tid = threadIdx.x;
    if (tid < 64) qs[tid] = q[m0 + tid];
    __syncthreads();
    const int tx = tid & 15, ty = tid >> 4;
    float acc[4][4];
#pragma unroll
    for (int i = 0; i < 4; i++)
#pragma unroll
        for (int j = 0; j < 4; j++) acc[i][j] = 0.0f;

    for (int k0 = 0; k0 < EE; k0 += 8) {
#pragma unroll
        for (int u = 0; u < 2; u++) {
            int lin = tid + u * 256;
            int r = lin >> 3, kk = lin & 7;
            int k = k0 + kk;
            As[kk][r] = (k < EE) ? Ew[(size_t)qs[r] * EE + k] : 0.0f;
            Bs[kk][r] = (k < EE) ? Wt[(size_t)(n0 + r) * EE + k] : 0.0f;
        }
        __syncthreads();
#pragma unroll
        for (int kk = 0; kk < 8; kk++) {
            float a[4], b[4];
#pragma unroll
            for (int i = 0; i < 4; i++) a[i] = As[kk][ty * 4 + i];
#pragma unroll
            for (int j = 0; j < 4; j++) b[j] = Bs[kk][tx * 4 + j];
#pragma unroll
            for (int i = 0; i < 4; i++)
#pragma unroll
                for (int j = 0; j < 4; j++) acc[i][j] += a[i] * b[j];
        }
        __syncthreads();
    }
#pragma unroll
    for (int i = 0; i < 4; i++) {
        int m = m0 + ty * 4 + i;
#pragma unroll
        for (int j = 0; j < 4; j++) {
            int n = n0 + tx * 4 + j;
            D[(size_t)m * G4 + n] = acc[i][j] + bias[n];
        }
    }
}

// ------------- fused LSTM step: gate GEMM (+preact/bias) + cell -----------
// Block tile: 64 batch rows x 16 hidden (4 gates gathered), 256 threads.
// gates[m, g*H + j] = pre[m, g*H+j] + bias[g*H+j]
//                   + sum_k x[m,k]*Wx[g*H+j,k] + sum_k hin[m,k]*Whh[g*H+j,k]
__global__ __launch_bounds__(256) void lstm_step_kernel(
    const float* __restrict__ pre, int pre_stride,      // may be null
    const float* __restrict__ x, const float* __restrict__ Wx,  // may be null
    const float* __restrict__ hin, const float* __restrict__ Whh,
    const float* __restrict__ bias,                      // may be null
    float* __restrict__ c, float* __restrict__ hout,
    const int* __restrict__ lengths, int t, int ncq)
{
    __shared__ float As[8][64];   // src rows  [k][m]
    __shared__ float Ws[8][64];   // W gathered [k][g*16+j]
    const int j0 = blockIdx.x * 16;
    const int m0 = blockIdx.y * 64;
    const int tid = threadIdx.x;
    const int tx = tid & 15, ty = tid >> 4;

    float acc[4][4];   // [gate][tm]
#pragma unroll
    for (int g = 0; g < 4; g++)
#pragma unroll
        for (int i = 0; i < 4; i++) acc[g][i] = 0.0f;

    const int r   = (tid & 127) >> 1;   // 0..63
    const int kq  = (tid & 1) * 4;
    const bool isA = (tid < 128);
    // gathered W row for the Ws loader
    const int wg = r >> 4, wj = r & 15;
    const int wn = wg * HH + j0 + wj;

#pragma unroll 1
    for (int s = 0; s < 2; s++) {
        const float* src = (s == 0) ? x : hin;
        const float* W   = (s == 0) ? Wx : Whh;
        if (src == nullptr) continue;
        for (int k0 = 0; k0 < HH; k0 += 8) {
            if (isA) {
                float4 v = *(const float4*)&src[(size_t)(m0 + r) * HH + k0 + kq];
                As[kq + 0][r] = v.x; As[kq + 1][r] = v.y;
                As[kq + 2][r] = v.z; As[kq + 3][r] = v.w;
            } else {
                float4 v = *(const float4*)&W[(size_t)wn * HH + k0 + kq];
                Ws[kq + 0][r] = v.x; Ws[kq + 1][r] = v.y;
                Ws[kq + 2][r] = v.z; Ws[kq + 3][r] = v.w;
            }
            __syncthreads();
#pragma unroll
            for (int kk = 0; kk < 8; kk++) {
                float4 a = *(const float4*)&As[kk][ty * 4];
                float w0 = Ws[kk][tx];
                float w1 = Ws[kk][16 + tx];
                float w2 = Ws[kk][32 + tx];
                float w3 = Ws[kk][48 + tx];
                acc[0][0] += a.x * w0; acc[0][1] += a.y * w0; acc[0][2] += a.z * w0; acc[0][3] += a.w * w0;
                acc[1][0] += a.x * w1; acc[1][1] += a.y * w1; acc[1][2] += a.z * w1; acc[1][3] += a.w * w1;
                acc[2][0] += a.x * w2; acc[2][1] += a.y * w2; acc[2][2] += a.z * w2; acc[2][3] += a.w * w2;
                acc[3][0] += a.x * w3; acc[3][1] += a.y * w3; acc[3][2] += a.z * w3; acc[3][3] += a.w * w3;
            }
            __syncthreads();
        }
    }

    const int j = j0 + tx;
#pragma unroll
    for (int tm = 0; tm < 4; tm++) {
        int m = m0 + ty * 4 + tm;
        float gi = acc[0][tm], gf = acc[1][tm], gg = acc[2][tm], go = acc[3][tm];
        if (pre) {
            const float* p = pre + (size_t)m * pre_stride;
            gi += p[j]; gf += p[HH + j]; gg += p[2 * HH + j]; go += p[3 * HH + j];
        }
        if (bias) {
            gi += bias[j]; gf += bias[HH + j]; gg += bias[2 * HH + j]; go += bias[3 * HH + j];
        }
        float co = c[(size_t)m * HH + j];
        float cn = sigf(gf) * co + sigf(gi) * tanhf(gg);
        float hn = sigf(go) * tanhf(cn);
        bool upd = true;
        if (lengths) upd = (t < lengths[m / ncq]);
        if (upd) c[(size_t)m * HH + j] = cn;
        hout[(size_t)m * HH + j] = upd ? hn : hin[(size_t)m * HH + j];
    }
}

// ---------------- small helpers ----------------
__global__ void zero_video_states_kernel() {
    int i = blockIdx.x * 256 + threadIdx.x;
    if (i < BB * HH) {
        g_vh1[0][i] = 0.0f; g_vc1[i] = 0.0f;
        g_vh2[0][i] = 0.0f; g_vc2[i] = 0.0f;
    }
}

__global__ void bcast_kernel() {
    int idx = blockIdx.x * 256 + threadIdx.x;
    if (idx < BT * HH) {
        int m = idx >> 9;          // row in [0,320)
        int j = idx & 511;
        int b = m / NCQ;
        g_th1[0][idx] = g_vh1[0][b * HH + j];
        g_tc1[idx]    = g_vc1[b * HH + j];
        g_th2[0][idx] = g_vh2[0][b * HH + j];
        g_tc2[idx]    = g_vc2[b * HH + j];
    }
}

// wc[k] = sum_j dec2_w[j] * dec1_w[j,k];  bc = dec2_w . dec1_b + dec2_b
__global__ void dec_combine_kernel(
    const float* __restrict__ dec1_w, const float* __restrict__ dec1_b,
    const float* __restrict__ dec2_w, const float* __restrict__ dec2_b)
{
    int k = blockIdx.x * 256 + threadIdx.x;
    if (k < 2 * HH) {
        float s = 0.0f;
        for (int j = 0; j < 2 * HH; j++) s += dec2_w[j] * dec1_w[(size_t)j * (2 * HH) + k];
        g_wc[k] = s;
    }
    if (k == 0) {
        float sb = dec2_b[0];
        for (int j = 0; j < 2 * HH; j++) sb += dec2_w[j] * dec1_b[j];
        g_bc[0] = sb;
    }
}

__global__ void final_out_kernel(float* __restrict__ out) {
    int m = blockIdx.x;      // 0..319
    int tid = threadIdx.x;   // 256
    float s = 0.0f;
    for (int k = tid; k < HH; k += 256) {
        s += g_th1[0][(size_t)m * HH + k] * g_wc[k];
        s += g_th2[0][(size_t)m * HH + k] * g_wc[HH + k];
    }
#pragma unroll
    for (int off = 16; off > 0; off >>= 1) s += __shfl_down_sync(0xffffffffu, s, off);
    __shared__ float red[8];
    if ((tid & 31) == 0) red[tid >> 5] = s;
    __syncthreads();
    if (tid == 0) {
        float tot = 0.0f;
        for (int w = 0; w < 8; w++) tot += red[w];
        out[m] = tot + g_bc[0];
    }
}

__global__ void argmax_kernel(float* __restrict__ out) {
    int b = threadIdx.x;
    if (b < BB) {
        float best = out[b * NCQ];
        int bi = 0;
        for (int nc = 1; nc < NCQ; nc++) {
            float v = out[b * NCQ + nc];
            if (v > best) { best = v; bi = nc; }
        }
        out[BT + b] = (float)bi;
    }
}

// ---------------- launch ----------------
extern "C" void kernel_launch(void* const* d_in, const int* in_sizes, int n_in,
                              void* d_out, int out_size)
{
    const float* vf      = (const float*)d_in[0];
    const int*   questions = (const int*)d_in[1];
    const int*   qlen    = (const int*)d_in[2];
    const float* embw    = (const float*)d_in[3];
    const float* Wih_t1  = (const float*)d_in[4];
    const float* Whh_t1  = (const float*)d_in[5];
    const float* b_t1    = (const float*)d_in[6];
    const float* Wih_t2  = (const float*)d_in[7];
    const float* Whh_t2  = (const float*)d_in[8];
    const float* b_t2    = (const float*)d_in[9];
    const float* Wih_v1  = (const float*)d_in[10];
    const float* Whh_v1  = (const float*)d_in[11];
    const float* b_v1    = (const float*)d_in[12];
    const float* Wih_v2  = (const float*)d_in[13];
    const float* Whh_v2  = (const float*)d_in[14];
    const float* b_v2    = (const float*)d_in[15];
    const float* dec1_w  = (const float*)d_in[16];
    const float* dec1_b  = (const float*)d_in[17];
    const float* dec2_w  = (const float*)d_in[18];
    const float* dec2_b  = (const float*)d_in[19];
    float* out = (float*)d_out;

    float *GAv, *GAt, *vh1, *vc1, *vh2, *vc2, *th1, *tc1, *th2, *tc2;
    cudaGetSymbolAddress((void**)&GAv, g_GAv);
    cudaGetSymbolAddress((void**)&GAt, g_GAt);
    cudaGetSymbolAddress((void**)&vh1, g_vh1);
    cudaGetSymbolAddress((void**)&vc1, g_vc1);
    cudaGetSymbolAddress((void**)&vh2, g_vh2);
    cudaGetSymbolAddress((void**)&vc2, g_vc2);
    cudaGetSymbolAddress((void**)&th1, g_th1);
    cudaGetSymbolAddress((void**)&tc1, g_tc1);
    cudaGetSymbolAddress((void**)&th2, g_th2);
    cudaGetSymbolAddress((void**)&tc2, g_tc2);

    // init video states
    zero_video_states_kernel<<<(BB * HH + 255) / 256, 256>>>();

    // precompute input projections
    sgemm_nt_kernel<<<dim3(G4 / 128, (BB * FF) / 128), 256>>>(
        BB * FF, G4, CC, vf, Wih_v1, b_v1, GAv);
    embgemm_kernel<<<dim3(G4 / 64, (BT * LQ) / 64), 256>>>(
        questions, embw, Wih_t1, b_t1, GAt);

    // ---- video recurrence: 20 steps, batch 64 ----
    int p = 0;
    for (int t = 0; t < FF; t++) {
        lstm_step_kernel<<<dim3(HH / 16, 1), 256>>>(
            GAv + (size_t)t * G4, FF * G4,
            nullptr, nullptr,
            vh1 + p * BB * HH, Whh_v1,
            nullptr,
            vc1, vh1 + (1 - p) * BB * HH,
            nullptr, 0, 1);
        lstm_step_kernel<<<dim3(HH / 16, 1), 256>>>(
            nullptr, 0,
            vh1 + (1 - p) * BB * HH, Wih_v2,
            vh2 + p * BB * HH, Whh_v2,
            b_v2,
            vc2, vh2 + (1 - p) * BB * HH,
            nullptr, 0, 1);
        p ^= 1;
    }
    // after 20 steps final states are in buffer 0

    // seed text states from video states (broadcast over NC)
    bcast_kernel<<<(BT * HH + 255) / 256, 256>>>();

    // ---- text recurrence: 20 steps, batch 320, ragged mask ----
    p = 0;
    for (int t = 0; t < LQ; t++) {
        lstm_step_kernel<<<dim3(HH / 16, BT / 64), 256>>>(
            GAt + (size_t)t * G4, LQ * G4,
            nullptr, nullptr,
            th1 + p * BT * HH, Whh_t1,
            nullptr,
            tc1, th1 + (1 - p) * BT * HH,
            qlen, t, NCQ);
        lstm_step_kernel<<<dim3(HH / 16, BT / 64), 256>>>(
            nullptr, 0,
            th1 + (1 - p) * BT * HH, Wih_t2,
            th2 + p * BT * HH, Whh_t2,
            b_t2,
            tc2, th2 + (1 - p) * BT * HH,
            qlen, t, NCQ);
        p ^= 1;
    }

    // ---- collapsed decoder + argmax ----
    dec_combine_kernel<<<(2 * HH + 255) / 256, 256>>>(dec1_w, dec1_b, dec2_w, dec2_b);
    final_out_kernel<<<BT, 256>>>(out);
    if (out_size > BT) argmax_kernel<<<1, 64>>>(out);
}

// round 4
// speedup vs baseline: 1.1654x; 1.1654x over previous
#include <cuda_runtime.h>
#include <cstdint>

// Problem constants
#define BB   64      // batch
#define NCQ  5       // questions per sample
#define LQ   20      // question length
#define FF   20      // video frames
#define CC   8192    // video feature dim
#define EE   300     // embed dim
#define HH   512     // hidden
#define G4   2048    // 4*H
#define BT   320     // B*NC

// ---------------- scratch (device globals; allocation-free) ----------------
__device__ float g_GAv[BB * FF * G4];   // video layer1 input preacts [b][f][4H]
__device__ float g_GAt[BT * LQ * G4];   // text  layer1 input preacts [bnc][l][4H]
__device__ float g_vh1[2][BB * HH];
__device__ float g_vc1[BB * HH];
__device__ float g_vh2[2][BB * HH];
__device__ float g_vc2[BB * HH];
__device__ float g_th1[2][BT * HH];
__device__ float g_tc1[BT * HH];
__device__ float g_th2[2][BT * HH];
__device__ float g_tc2[BT * HH];
__device__ float g_wc[2 * HH];
__device__ float g_bc[1];

__device__ __forceinline__ float sigf(float x) { return 1.0f / (1.0f + __expf(-x)); }

// ---------------- packed f32x2 helpers (Blackwell 2x fp32 path) -----------
__device__ __forceinline__ unsigned long long pk2(float x, float y) {
    unsigned long long r;
    asm("mov.b64 %0, {%1, %2};" : "=l"(r) : "f"(x), "f"(y));
    return r;
}
__device__ __forceinline__ void fma2(unsigned long long& d,
                                     unsigned long long a,
                                     unsigned long long b) {
    asm("fma.rn.f32x2 %0, %1, %2, %0;" : "+l"(d) : "l"(a), "l"(b));
}
__device__ __forceinline__ float2 up2(unsigned long long v) {
    float x, y;
    asm("mov.b64 {%0, %1}, %2;" : "=f"(x), "=f"(y) : "l"(v));
    return make_float2(x, y);
}

// ---------------- big NT SGEMM: D[m,n] = bias[n] + sum_k A[m,k]*W[n,k] -----
// 128x128xK16 tiles, 256 threads, 8x8 microtile (split-j), double-buffered,
// f32x2 packed math. M,N,K multiples of 128/128/16.
__global__ __launch_bounds__(256) void sgemm_nt_kernel(
    int M, int N, int K,
    const float* __restrict__ A,
    const float* __restrict__ W,
    const float* __restrict__ bias,
    float* __restrict__ D)
{
    __shared__ __align__(16) float As[2][16][128];
    __shared__ __align__(16) float Bs[2][16][128];
    const int m0 = blockIdx.y * 128;
    const int n0 = blockIdx.x * 128;
    const int tid = threadIdx.x;
    const int tx = tid & 15;          // 0..15 -> j columns tx*4 and 64+tx*4
    const int ty = tid >> 4;          // 0..15 -> m rows ty*8 .. +7

    unsigned long long acc2[8][4];
#pragma unroll
    for (int i = 0; i < 8; i++)
#pragma unroll
        for (int j = 0; j < 4; j++) acc2[i][j] = 0ull;

    // loader mapping: two float4 per matrix per thread
    int lrow[2], lkq[2];
#pragma unroll
    for (int u = 0; u < 2; u++) {
        int idx = tid + u * 256;       // 0..511
        lrow[u] = idx >> 2;            // 0..127
        lkq[u]  = (idx & 3) * 4;       // 0,4,8,12
    }

    float4 ra[2], rb[2];
    // preload tile 0
#pragma unroll
    for (int u = 0; u < 2; u++) {
        ra[u] = *(const float4*)&A[(size_t)(m0 + lrow[u]) * K + lkq[u]];
        rb[u] = *(const float4*)&W[(size_t)(n0 + lrow[u]) * K + lkq[u]];
    }
#pragma unroll
    for (int u = 0; u < 2; u++) {
        As[0][lkq[u] + 0][lrow[u]] = ra[u].x; As[0][lkq[u] + 1][lrow[u]] = ra[u].y;
        As[0][lkq[u] + 2][lrow[u]] = ra[u].z; As[0][lkq[u] + 3][lrow[u]] = ra[u].w;
        Bs[0][lkq[u] + 0][lrow[u]] = rb[u].x; Bs[0][lkq[u] + 1][lrow[u]] = rb[u].y;
        Bs[0][lkq[u] + 2][lrow[u]] = rb[u].z; Bs[0][lkq[u] + 3][lrow[u]] = rb[u].w;
    }
    __syncthreads();

    const int ntiles = K >> 4;
    for (int it = 0; it < ntiles; it++) {
        const int cur = it & 1;
        if (it + 1 < ntiles) {
            const int k0 = (it + 1) << 4;
#pragma unroll
            for (int u = 0; u < 2; u++) {
                ra[u] = *(const float4*)&A[(size_t)(m0 + lrow[u]) * K + k0 + lkq[u]];
                rb[u] = *(const float4*)&W[(size_t)(n0 + lrow[u]) * K + k0 + lkq[u]];
            }
        }
#pragma unroll
        for (int kk = 0; kk < 16; kk++) {
            float4 a0 = *(const float4*)&As[cur][kk][ty * 8];
            float4 a1 = *(const float4*)&As[cur][kk][ty * 8 + 4];
            float4 b0 = *(const float4*)&Bs[cur][kk][tx * 4];        // j = tx*4 ..
            float4 b1 = *(const float4*)&Bs[cur][kk][64 + tx * 4];   // j = 64+tx*4 ..
            unsigned long long bp[4] = {
                pk2(b0.x, b0.y), pk2(b0.z, b0.w),
                pk2(b1.x, b1.y), pk2(b1.z, b1.w)
            };
            float av[8] = {a0.x, a0.y, a0.z, a0.w, a1.x, a1.y, a1.z, a1.w};
#pragma unroll
            for (int i = 0; i < 8; i++) {
                unsigned long long ad = pk2(av[i], av[i]);
#pragma unroll
                for (int j = 0; j < 4; j++) fma2(acc2[i][j], ad, bp[j]);
            }
        }
        if (it + 1 < ntiles) {
            const int nb = cur ^ 1;
#pragma unroll
            for (int u = 0; u < 2; u++) {
                As[nb][lkq[u] + 0][lrow[u]] = ra[u].x; As[nb][lkq[u] + 1][lrow[u]] = ra[u].y;
                As[nb][lkq[u] + 2][lrow[u]] = ra[u].z; As[nb][lkq[u] + 3][lrow[u]] = ra[u].w;
                Bs[nb][lkq[u] + 0][lrow[u]] = rb[u].x; Bs[nb][lkq[u] + 1][lrow[u]] = rb[u].y;
                Bs[nb][lkq[u] + 2][lrow[u]] = rb[u].z; Bs[nb][lkq[u] + 3][lrow[u]] = rb[u].w;
            }
        }
        __syncthreads();
    }

    // epilogue: columns tx*4..+3 and 64+tx*4..+3
#pragma unroll
    for (int i = 0; i < 8; i++) {
        const int m = m0 + ty * 8 + i;
#pragma unroll
        for (int half = 0; half < 2; half++) {
            const int n = n0 + half * 64 + tx * 4;
            float2 v0 = up2(acc2[i][half * 2 + 0]);
            float2 v1 = up2(acc2[i][half * 2 + 1]);
            D[(size_t)m * N + n + 0] = v0.x + bias[n + 0];
            D[(size_t)m * N + n + 1] = v0.y + bias[n + 1];
            D[(size_t)m * N + n + 2] = v1.x + bias[n + 2];
            D[(size_t)m * N + n + 3] = v1.y + bias[n + 3];
        }
    }
}

// ------------- embedding-gather GEMM (text layer1 input preacts) ----------
// D[m,n] = b[n] + sum_k Ew[q[m],k] * Wt[n,k]; M=6400, N=2048, K=300=25*12.
// 128x128xK12 tiles, float4 loads, f32x2 math.
__global__ __launch_bounds__(256) void embgemm_kernel(
    const int* __restrict__ q,
    const float* __restrict__ Ew,
    const float* __restrict__ Wt,
    const float* __restrict__ bias,
    float* __restrict__ D)
{
    __shared__ int qs[128];
    __shared__ __align__(16) float As[12][128];
    __shared__ __align__(16) float Bs[12][128];
    const int m0 = blockIdx.y * 128;
    const int n0 = blockIdx.x * 128;
    const int tid = threadIdx.x;
    if (tid < 128) qs[tid] = q[m0 + tid];
    __syncthreads();
    const int tx = tid & 15, ty = tid >> 4;

    unsigned long long acc2[8][4];
#pragma unroll
    for (int i = 0; i < 8; i++)
#pragma unroll
        for (int j = 0; j < 4; j++) acc2[i][j] = 0ull;

    for (int k0 = 0; k0 < EE; k0 += 12) {
#pragma unroll
        for (int u = 0; u < 2; u++) {
            int idx = tid + u * 256;
            if (idx < 384) {
                int row = idx / 3;
                int kq  = (idx % 3) * 4;
                float4 av = *(const float4*)&Ew[(size_t)qs[row] * EE + k0 + kq];
                float4 bv = *(const float4*)&Wt[(size_t)(n0 + row) * EE + k0 + kq];
                As[kq + 0][row] = av.x; As[kq + 1][row] = av.y;
                As[kq + 2][row] = av.z; As[kq + 3][row] = av.w;
                Bs[kq + 0][row] = bv.x; Bs[kq + 1][row] = bv.y;
                Bs[kq + 2][row] = bv.z; Bs[kq + 3][row] = bv.w;
            }
        }
        __syncthreads();
#pragma unroll
        for (int kk = 0; kk < 12; kk++) {
            float4 a0 = *(const float4*)&As[kk][ty * 8];
            float4 a1 = *(const float4*)&As[kk][ty * 8 + 4];
            float4 b0 = *(const float4*)&Bs[kk][tx * 4];
            float4 b1 = *(const float4*)&Bs[kk][64 + tx * 4];
            unsigned long long bp[4] = {
                pk2(b0.x, b0.y), pk2(b0.z, b0.w),
                pk2(b1.x, b1.y), pk2(b1.z, b1.w)
            };
            float av[8] = {a0.x, a0.y, a0.z, a0.w, a1.x, a1.y, a1.z, a1.w};
#pragma unroll
            for (int i = 0; i < 8; i++) {
                unsigned long long ad = pk2(av[i], av[i]);
#pragma unroll
                for (int j = 0; j < 4; j++) fma2(acc2[i][j], ad, bp[j]);
            }
        }
        __syncthreads();
    }

#pragma unroll
    for (int i = 0; i < 8; i++) {
        const int m = m0 + ty * 8 + i;
#pragma unroll
        for (int half = 0; half < 2; half++) {
            const int n = n0 + half * 64 + tx * 4;
            float2 v0 = up2(acc2[i][half * 2 + 0]);
            float2 v1 = up2(acc2[i][half * 2 + 1]);
            D[(size_t)m * G4 + n + 0] = v0.x + bias[n + 0];
            D[(size_t)m * G4 + n + 1] = v0.y + bias[n + 1];
            D[(size_t)m * G4 + n + 2] = v1.x + bias[n + 2];
            D[(size_t)m * G4 + n + 3] = v1.y + bias[n + 3];
        }
    }
}

// ------------- fused LSTM step: gate GEMM (+preact/bias) + cell -----------
// Block tile: 64 batch rows x (4 gates x JT hidden), 256 threads, K-tile 16,
// f32x2 packed math (pairs along m). JT in {8,16}.
// gates[m, g*H + j] = pre[m, g*H+j] + bias[g*H+j]
//                   + sum_k x[m,k]*Wx[g*H+j,k] + sum_k hin[m,k]*Whh[g*H+j,k]
template<int JT>
__global__ __launch_bounds__(256) void lstm_step_t(
    const float* __restrict__ pre, int pre_stride,      // may be null
    const float* __restrict__ x, const float* __restrict__ Wx,  // may be null
    const float* __restrict__ hin, const float* __restrict__ Whh,
    const float* __restrict__ bias,                      // may be null
    float* __restrict__ c, float* __restrict__ hout,
    const int* __restrict__ lengths, int t, int ncq)
{
    constexpr int RPT = JT / 4;       // rows per thread: 4 (JT=16) or 2 (JT=8)
    constexpr int NW  = 4 * JT;       // gathered W rows per block
    __shared__ __align__(16) float As[16][64];
    __shared__ __align__(16) float Ws[16][NW];

    const int j0 = blockIdx.x * JT;
    const int m0 = blockIdx.y * 64;
    const int tid = threadIdx.x;
    const int tx = tid % JT;          // hidden index within tile
    const int rg = tid / JT;          // row group

    // As loader: 256 float4 (64 rows x 4), one per thread
    const int arow = tid >> 2, akq = (tid & 3) * 4;
    // Ws loader: NW*4 float4 (<=256), thread tid handles f4 idx=tid if < NW*4
    const int wr = tid >> 2, wkq = (tid & 3) * 4;
    const int wg = wr / JT, wj = wr % JT;
    const int wrow = wg * HH + j0 + wj;
    const bool wload = (tid < NW * 4);

    unsigned long long acc2[4][RPT / 2];
#pragma unroll
    for (int g = 0; g < 4; g++)
#pragma unroll
        for (int p = 0; p < RPT / 2; p++) acc2[g][p] = 0ull;

#pragma unroll 1
    for (int s = 0; s < 2; s++) {
        const float* src = (s == 0) ? x : hin;
        const float* W   = (s == 0) ? Wx : Whh;
        if (src == nullptr) continue;
        for (int k0 = 0; k0 < HH; k0 += 16) {
            {
                float4 v = *(const float4*)&src[(size_t)(m0 + arow) * HH + k0 + akq];
                As[akq + 0][arow] = v.x; As[akq + 1][arow] = v.y;
                As[akq + 2][arow] = v.z; As[akq + 3][arow] = v.w;
            }
            if (wload) {
                float4 v = *(const float4*)&W[(size_t)wrow * HH + k0 + wkq];
                Ws[wkq + 0][wr] = v.x; Ws[wkq + 1][wr] = v.y;
                Ws[wkq + 2][wr] = v.z; Ws[wkq + 3][wr] = v.w;
            }
            __syncthreads();
#pragma unroll
            for (int kk = 0; kk < 16; kk++) {
                unsigned long long wd[4];
#pragma unroll
                for (int g = 0; g < 4; g++) {
                    float w = Ws[kk][g * JT + tx];
                    wd[g] = pk2(w, w);
                }
                unsigned long long ap[RPT / 2];
                if (RPT == 4) {
                    float4 av = *(const float4*)&As[kk][rg * 4];
                    ap[0] = pk2(av.x, av.y);
                    ap[RPT / 2 - 1] = pk2(av.z, av.w);   // ap[1]
                } else {
                    float2 av = *(const float2*)&As[kk][rg * 2];
                    ap[0] = pk2(av.x, av.y);
                }
#pragma unroll
                for (int g = 0; g < 4; g++)
#pragma unroll
                    for (int p = 0; p < RPT / 2; p++) fma2(acc2[g][p], wd[g], ap[p]);
            }
            __syncthreads();
        }
    }

    const int j = j0 + tx;
#pragma unroll
    for (int r = 0; r < RPT; r++) {
        const int m = m0 + rg * RPT + r;
        float gv[4];
#pragma unroll
        for (int g = 0; g < 4; g++) {
            float2 u = up2(acc2[g][r >> 1]);
            gv[g] = (r & 1) ? u.y : u.x;
        }
        float gi = gv[0], gf = gv[1], gg = gv[2], go = gv[3];
        if (pre) {
            const float* p = pre + (size_t)m * pre_stride;
            gi += p[j]; gf += p[HH + j]; gg += p[2 * HH + j]; go += p[3 * HH + j];
        }
        if (bias) {
            gi += bias[j]; gf += bias[HH + j]; gg += bias[2 * HH + j]; go += bias[3 * HH + j];
        }
        float co = c[(size_t)m * HH + j];
        float cn = sigf(gf) * co + sigf(gi) * tanhf(gg);
        float hn = sigf(go) * tanhf(cn);
        bool upd = true;
        if (lengths) upd = (t < lengths[m / ncq]);
        if (upd) c[(size_t)m * HH + j] = cn;
        hout[(size_t)m * HH + j] = upd ? hn : hin[(size_t)m * HH + j];
    }
}

// ---------------- small helpers ----------------
__global__ void zero_video_states_kernel() {
    int i = blockIdx.x * 256 + threadIdx.x;
    if (i < BB * HH) {
        g_vh1[0][i] = 0.0f; g_vc1[i] = 0.0f;
        g_vh2[0][i] = 0.0f; g_vc2[i] = 0.0f;
    }
}

__global__ void bcast_kernel() {
    int idx = blockIdx.x * 256 + threadIdx.x;
    if (idx < BT * HH) {
        int m = idx >> 9;          // row in [0,320)
        int j = idx & 511;
        int b = m / NCQ;
        g_th1[0][idx] = g_vh1[0][b * HH + j];
        g_tc1[idx]    = g_vc1[b * HH + j];
        g_th2[0][idx] = g_vh2[0][b * HH + j];
        g_tc2[idx]    = g_vc2[b * HH + j];
    }
}

// wc[k] = sum_j dec2_w[j] * dec1_w[j,k];  bc = dec2_w . dec1_b + dec2_b
__global__ void dec_combine_kernel(
    const float* __restrict__ dec1_w, const float* __restrict__ dec1_b,
    const float* __restrict__ dec2_w, const float* __restrict__ dec2_b)
{
    int k = blockIdx.x * 256 + threadIdx.x;
    if (k < 2 * HH) {
        float s = 0.0f;
        for (int j = 0; j < 2 * HH; j++) s += dec2_w[j] * dec1_w[(size_t)j * (2 * HH) + k];
        g_wc[k] = s;
    }
    if (k == 0) {
        float sb = dec2_b[0];
        for (int j = 0; j < 2 * HH; j++) sb += dec2_w[j] * dec1_b[j];
        g_bc[0] = sb;
    }
}

__global__ void final_out_kernel(float* __restrict__ out) {
    int m = blockIdx.x;      // 0..319
    int tid = threadIdx.x;   // 256
    float s = 0.0f;
    for (int k = tid; k < HH; k += 256) {
        s += g_th1[0][(size_t)m * HH + k] * g_wc[k];
        s += g_th2[0][(size_t)m * HH + k] * g_wc[HH + k];
    }
#pragma unroll
    for (int off = 16; off > 0; off >>= 1) s += __shfl_down_sync(0xffffffffu, s, off);
    __shared__ float red[8];
    if ((tid & 31) == 0) red[tid >> 5] = s;
    __syncthreads();
    if (tid == 0) {
        float tot = 0.0f;
        for (int w = 0; w < 8; w++) tot += red[w];
        out[m] = tot + g_bc[0];
    }
}

__global__ void argmax_kernel(float* __restrict__ out) {
    int b = threadIdx.x;
    if (b < BB) {
        float best = out[b * NCQ];
        int bi = 0;
        for (int nc = 1; nc < NCQ; nc++) {
            float v = out[b * NCQ + nc];
            if (v > best) { best = v; bi = nc; }
        }
        out[BT + b] = (float)bi;
    }
}

// ---------------- launch ----------------
extern "C" void kernel_launch(void* const* d_in, const int* in_sizes, int n_in,
                              void* d_out, int out_size)
{
    const float* vf        = (const float*)d_in[0];
    const int*   questions = (const int*)d_in[1];
    const int*   qlen      = (const int*)d_in[2];
    const float* embw      = (const float*)d_in[3];
    const float* Wih_t1    = (const float*)d_in[4];
    const float* Whh_t1    = (const float*)d_in[5];
    const float* b_t1      = (const float*)d_in[6];
    const float* Wih_t2    = (const float*)d_in[7];
    const float* Whh_t2    = (const float*)d_in[8];
    const float* b_t2      = (const float*)d_in[9];
    const float* Wih_v1    = (const float*)d_in[10];
    const float* Whh_v1    = (const float*)d_in[11];
    const float* b_v1      = (const float*)d_in[12];
    const float* Wih_v2    = (const float*)d_in[13];
    const float* Whh_v2    = (const float*)d_in[14];
    const float* b_v2      = (const float*)d_in[15];
    const float* dec1_w    = (const float*)d_in[16];
    const float* dec1_b    = (const float*)d_in[17];
    const float* dec2_w    = (const float*)d_in[18];
    const float* dec2_b    = (const float*)d_in[19];
    float* out = (float*)d_out;

    float *GAv, *GAt, *vh1, *vc1, *vh2, *vc2, *th1, *tc1, *th2, *tc2;
    cudaGetSymbolAddress((void**)&GAv, g_GAv);
    cudaGetSymbolAddress((void**)&GAt, g_GAt);
    cudaGetSymbolAddress((void**)&vh1, g_vh1);
    cudaGetSymbolAddress((void**)&vc1, g_vc1);
    cudaGetSymbolAddress((void**)&vh2, g_vh2);
    cudaGetSymbolAddress((void**)&vc2, g_vc2);
    cudaGetSymbolAddress((void**)&th1, g_th1);
    cudaGetSymbolAddress((void**)&tc1, g_tc1);
    cudaGetSymbolAddress((void**)&th2, g_th2);
    cudaGetSymbolAddress((void**)&tc2, g_tc2);

    // init video states
    zero_video_states_kernel<<<(BB * HH + 255) / 256, 256>>>();

    // precompute input projections
    sgemm_nt_kernel<<<dim3(G4 / 128, (BB * FF) / 128), 256>>>(
        BB * FF, G4, CC, vf, Wih_v1, b_v1, GAv);
    embgemm_kernel<<<dim3(G4 / 128, (BT * LQ) / 128), 256>>>(
        questions, embw, Wih_t1, b_t1, GAt);

    // decoder collapse can run any time before final_out
    dec_combine_kernel<<<(2 * HH + 255) / 256, 256>>>(dec1_w, dec1_b, dec2_w, dec2_b);

    // ---- video recurrence: 20 steps, batch 64 (JT=8 -> 64 blocks) ----
    int p = 0;
    for (int t = 0; t < FF; t++) {
        lstm_step_t<8><<<dim3(HH / 8, 1), 256>>>(
            GAv + (size_t)t * G4, FF * G4,
            nullptr, nullptr,
            vh1 + p * BB * HH, Whh_v1,
            nullptr,
            vc1, vh1 + (1 - p) * BB * HH,
            nullptr, 0, 1);
        lstm_step_t<8><<<dim3(HH / 8, 1), 256>>>(
            nullptr, 0,
            vh1 + (1 - p) * BB * HH, Wih_v2,
            vh2 + p * BB * HH, Whh_v2,
            b_v2,
            vc2, vh2 + (1 - p) * BB * HH,
            nullptr, 0, 1);
        p ^= 1;
    }
    // after 20 steps (even), final states are in buffer 0

    // seed text states from video states (broadcast over NC)
    bcast_kernel<<<(BT * HH + 255) / 256, 256>>>();

    // ---- text recurrence: 20 steps, batch 320, ragged mask (JT=16 -> 160 blocks) ----
    p = 0;
    for (int t = 0; t < LQ; t++) {
        lstm_step_t<16><<<dim3(HH / 16, BT / 64), 256>>>(
            GAt + (size_t)t * G4, LQ * G4,
            nullptr, nullptr,
            th1 + p * BT * HH, Whh_t1,
            nullptr,
            tc1, th1 + (1 - p) * BT * HH,
            qlen, t, NCQ);
        lstm_step_t<16><<<dim3(HH / 16, BT / 64), 256>>>(
            nullptr, 0,
            th1 + (1 - p) * BT * HH, Wih_t2,
            th2 + p * BT * HH, Whh_t2,
            b_t2,
            tc2, th2 + (1 - p) * BT * HH,
            qlen, t, NCQ);
        p ^= 1;
    }

    // ---- collapsed decoder + argmax ----
    final_out_kernel<<<BT, 256>>>(out);
    if (out_size > BT) argmax_kernel<<<1, 64>>>(out);
}